// round 15
// baseline (speedup 1.0000x reference)
#include <cuda_runtime.h>

// CRF log-likelihood: B=4096, T=512, K=13.
// Round-12/14 structure (8-lane groups, 4 groups/warp, split fwd/bwd halves,
// permuted states, lane-parallel numerator, hoisted emission exps)
// + TRIPLE-BUFFERED cp.async staging (prefetch distance 2 chunks).
#define B_ 4096
#define T_ 512
#define K_ 13
#define GSTRIDE 544

__device__ __align__(16) float g_svF[B_][16];
__device__ float g_numF[B_];
__device__ int   g_mexF[B_], g_lastF[B_];
__device__ volatile int g_flag[B_];
__device__ unsigned long long g_acc = 0;
__device__ unsigned int       g_cnt = 0;

__device__ __forceinline__ void cp16(unsigned dst, const void* src) {
    asm volatile("cp.async.cg.shared.global [%0], [%1], 16;\n" :: "r"(dst), "l"(src));
}
__device__ __forceinline__ void cp8(unsigned dst, const void* src) {
    asm volatile("cp.async.ca.shared.global [%0], [%1], 8;\n" :: "r"(dst), "l"(src));
}
__device__ __forceinline__ void cp_commit() { asm volatile("cp.async.commit_group;\n"); }
template<int N> __device__ __forceinline__ void cp_wait() {
    asm volatile("cp.async.wait_group %0;\n" :: "n"(N));
}
__device__ __forceinline__ unsigned long long pk2(float lo, float hi) {
    unsigned long long r;
    asm("mov.b64 %0,{%1,%2};" : "=l"(r) : "f"(lo), "f"(hi));
    return r;
}
__device__ __forceinline__ void upk2(unsigned long long v, float& lo, float& hi) {
    asm("mov.b64 {%0,%1},%2;" : "=f"(lo), "=f"(hi) : "l"(v));
}
__device__ __forceinline__ unsigned long long mul2(unsigned long long a, unsigned long long b) {
    unsigned long long d;
    asm("mul.rn.f32x2 %0,%1,%2;" : "=l"(d) : "l"(a), "l"(b));
    return d;
}
__device__ __forceinline__ unsigned long long fma2(unsigned long long a, unsigned long long b,
                                                   unsigned long long c) {
    unsigned long long d;
    asm("fma.rn.f32x2 %0,%1,%2,%3;" : "=l"(d) : "l"(a), "l"(b), "l"(c));
    return d;
}
__device__ __forceinline__ unsigned long long add2(unsigned long long a, unsigned long long b) {
    unsigned long long d;
    asm("add.rn.f32x2 %0,%1,%2;" : "=l"(d) : "l"(a), "l"(b));
    return d;
}
__device__ __forceinline__ int ORIG(int n) { return n < 12 ? n + 1 : (n == 12 ? 0 : -1); }

__device__ __forceinline__ bool mask_ones(const unsigned char* gb, int msh) {
    const unsigned long long* mw = (const unsigned long long*)(gb + 480);
    if (msh) return (mw[0] == 0x0000000100000001ULL) & (mw[1] == 0x0000000100000001ULL)
                  & (mw[2] == 0x0000000100000001ULL) & (mw[3] == 0x0000000100000001ULL);
    return mw[0] == 0x0101010101010101ULL;
}

#define STORE2(W, a, b)                                                       \
    asm volatile("st.shared.v2.f32 [%0],{%1,%2};"                             \
                 :: "r"(xch_addr + (W) * 320 + l * 8), "f"(a), "f"(b) : "memory");
#define STORE1(W, a)                                                          \
    asm volatile("st.shared.f32 [%0],%1;"                                     \
                 :: "r"(xch_addr + (W) * 320 + l * 4), "f"(a) : "memory");

__global__ void __launch_bounds__(128) crf_half_kernel(
    const float* __restrict__ emissions,
    const int* __restrict__ tags_words,
    const unsigned char* __restrict__ mask_b,
    const unsigned int* __restrict__ mask_words,
    const float* __restrict__ start_t,
    const float* __restrict__ end_t,
    const float* __restrict__ trans,
    float* __restrict__ out)
{
    __shared__ float sm_trans[K_ * K_];
    __shared__ float sm_start[K_];
    __shared__ float sm_end[K_];
    __shared__ __align__(16) unsigned char stage[4 * 3 * 4 * GSTRIDE];  // warp,buf,group
    __shared__ __align__(16) float s_xch[4 * 2 * 4 * 20];
    __shared__ int s_t64, s_m32;

    const int tid = threadIdx.x;
    if (tid == 0) { s_t64 = 1; s_m32 = 1; }
    for (int i = tid; i < K_ * K_; i += 128) sm_trans[i] = trans[i];
    if (tid < K_) { sm_start[tid] = start_t[tid]; sm_end[tid] = end_t[tid]; }
    __syncthreads();
    if (tid < 64 && tags_words[2 * tid + 1] != 0) s_t64 = 0;
    if (mask_words[(blockIdx.x & 255) * 2048 + tid * 8] > 1u) s_m32 = 0;
    __syncthreads();
    const int tshift = s_t64 ? 1 : 0;
    const int msh    = s_m32 ? 2 : 0;

    const bool isF = (blockIdx.x < 256);
    const int bblk = blockIdx.x & 255;
    const int lane = tid & 31;
    const int warp = tid >> 5;
    const int g    = lane >> 3;
    const int l    = lane & 7;
    const int batch = (bblk * 4 + warp) * 4 + g;

    const size_t tbase = (size_t)batch * T_;
    const int oA = ORIG(2 * l);
    const int oB = ORIG(2 * l + 1);
    const bool vA_ = (oA >= 0);
    const bool vB_ = (oB >= 0);
    const int oAl = vA_ ? oA : 0;
    const int oBl = vB_ ? oB : 0;

    const float* __restrict__ row = emissions + (size_t)batch * (T_ * K_);

    // triple-buffered stage for this (warp, group)
    unsigned char* bufp[3];
    unsigned bufs_[3];
#pragma unroll
    for (int i = 0; i < 3; i++) {
        bufp[i]  = stage + (size_t)(((warp * 3 + i) * 4) + g) * GSTRIDE;
        bufs_[i] = (unsigned)__cvta_generic_to_shared(bufp[i]);
    }
    const unsigned xch_addr =
        (unsigned)__cvta_generic_to_shared(s_xch) + warp * 640 + g * 80;

#define COPY_ROWS(R0, dsts)                                                   \
    {                                                                         \
        const char* esrc = (const char*)row + (size_t)(R0) * (K_ * 4);        \
        _Pragma("unroll")                                                     \
        for (int it = 0; it < 4; it++) {                                      \
            int idx = l + it * 8;                                             \
            if (idx < 26) cp16((dsts) + idx * 16, esrc + idx * 16);           \
        }                                                                     \
        if (tshift) { if (l < 4) cp16((dsts) + 416 + l * 16,                  \
            (const char*)tags_words + (((size_t)(tbase + (R0))) << 3) + l*16); } \
        else        { if (l < 2) cp16((dsts) + 416 + l * 16,                  \
            (const char*)tags_words + (((size_t)(tbase + (R0))) << 2) + l*16); } \
        if (msh)    { if (l < 2) cp16((dsts) + 480 + l * 16,                  \
            mask_b + (((size_t)(tbase + (R0))) << 2) + l * 16); }             \
        else        { if (l == 0) cp8((dsts) + 480, mask_b + (tbase + (R0))); } \
        cp_commit();                                                          \
    }

    float numL = 0.0f;

    if (isF) {
        // ======== FORWARD: t = 0 .. 255 (copy chunks 0..30, base 8+8c) ========
        unsigned long long etpA[8];
#pragma unroll
        for (int i = 0; i < 8; i++) {
            int r0 = ORIG(2 * i), r1 = ORIG(2 * i + 1);
            float a0 = (vA_ && r0 >= 0) ? __expf(sm_trans[r0 * K_ + oA]) : 0.0f;
            float a1 = (vA_ && r1 >= 0) ? __expf(sm_trans[r1 * K_ + oA]) : 0.0f;
            etpA[i] = pk2(a0, a1);
        }
        const float cB0 = vB_ ? __expf(sm_trans[oA * K_ + oB]) : 0.0f;
        const float cB1 = vB_ ? __expf(sm_trans[oB * K_ + oB]) : 0.0f;

        float sA = vA_ ? __expf(sm_start[oAl] + row[oAl]) : 0.0f;
        float sB = vB_ ? __expf(sm_start[oBl] + row[oBl]) : 0.0f;
        int Mexp;
        {
            float rawO = __expf(sm_start[0] + row[0]);
            int eb = (__float_as_int(rawO) >> 23) & 255;
            float sc = __int_as_float((254 - eb) << 23);
            sA *= sc; sB *= sc; Mexp = eb - 127;
        }
        int tg0 = tags_words[tbase << tshift];
        float num = sm_start[tg0] + row[tg0];
        int prev = tg0, last = tg0;
        STORE2(0, sA, sB);

#define STEPF_MV(W)                                                           \
        float mA, mB;                                                         \
        {                                                                     \
            unsigned _ra = xch_addr + (((W) ^ 1) * 320);                      \
            unsigned long long q0,q1,q2,q3,q4,q5,q6,q7;                       \
            asm volatile("ld.shared.v2.u64 {%0,%1},[%2];"                     \
                         : "=l"(q0),"=l"(q1) : "r"(_ra));                     \
            asm volatile("ld.shared.v2.u64 {%0,%1},[%2+16];"                  \
                         : "=l"(q2),"=l"(q3) : "r"(_ra));                     \
            asm volatile("ld.shared.v2.u64 {%0,%1},[%2+32];"                  \
                         : "=l"(q4),"=l"(q5) : "r"(_ra));                     \
            asm volatile("ld.shared.v2.u64 {%0,%1},[%2+48];"                  \
                         : "=l"(q6),"=l"(q7) : "r"(_ra));                     \
            unsigned long long a0 = mul2(q0, etpA[0]);                        \
            unsigned long long a1 = mul2(q1, etpA[1]);                        \
            a0 = fma2(q2, etpA[2], a0);  a1 = fma2(q3, etpA[3], a1);          \
            a0 = fma2(q4, etpA[4], a0);  a1 = fma2(q5, etpA[5], a1);          \
            a0 = fma2(q6, etpA[6], a0);  a1 = fma2(q7, etpA[7], a1);          \
            float xA, yA;  upk2(add2(a0, a1), xA, yA);                        \
            mA = xA + yA;                                                     \
            mB = fmaf(cB1, sB, cB0 * sA);                                     \
        }
#define STEPF_STX(W, exa, exb) {                                              \
        STEPF_MV(W);                                                          \
        sA = (exa) * mA;  sB = (exb) * mB;                                    \
        STORE2(W, sA, sB); }
#define STEPF_GEN(W, eAv, eBv, tgv, mkv, rtv) {                               \
        STEPF_MV(W);                                                          \
        float rA = __expf(eAv) * mA;                                          \
        float rB = __expf(eBv) * mB;                                          \
        bool _mk = (mkv) != 0;                                                \
        sA = _mk ? rA : sA;  sB = _mk ? rB : sB;                              \
        num += _mk ? (sm_trans[prev * K_ + (tgv)] + (rtv)) : 0.0f;            \
        last = _mk ? (tgv) : last;  prev = (tgv);                             \
        STORE2(W, sA, sB); }
#define RENORMF(W) {                                                          \
        float sO;                                                             \
        asm volatile("ld.shared.f32 %0,[%1];"                                 \
                     : "=f"(sO) : "r"(xch_addr + (W) * 320 + 48));            \
        int ebx = (__float_as_int(sO) >> 23) & 255;                           \
        float scx = __int_as_float((254 - ebx) << 23);                        \
        sA *= scx; sB *= scx; Mexp += ebx - 127;                              \
        STORE2(W, sA, sB); }

        COPY_ROWS(8,  bufs_[0]);   // chunk 0
        COPY_ROWS(16, bufs_[1]);   // chunk 1
#pragma unroll
        for (int t = 1; t < 8; t++) {
            const float* r = row + t * K_;
            int tg = tags_words[(tbase + t) << tshift];
            int mk = mask_b[(tbase + t) << msh];
            float eA = r[oAl];
            float eB = r[oBl];
            float rt = r[tg];
            STEPF_GEN(t & 1, eA, eB, tg, mk, rt);
        }
        RENORMF(1);
        int tagPrev = prev;

        for (int c = 0; c < 31; c++) {
            int cn = (c + 2 < 31) ? c + 2 : 30;            // dup-commit at tail
            COPY_ROWS(8 + 8 * cn, bufs_[(c + 2) % 3]);
            cp_wait<2>();                                   // chunk c guaranteed
            __syncwarp();
            const unsigned char* gb = bufp[c % 3];
            if (mask_ones(gb, msh)) {
                float exA[8], exB[8];
#pragma unroll
                for (int u = 0; u < 8; u++) {
                    exA[u] = __expf(*(const float*)(gb + u * 52 + oAl * 4));
                    exB[u] = __expf(*(const float*)(gb + u * 52 + oBl * 4));
                }
#pragma unroll
                for (int u = 0; u < 8; u++)
                    STEPF_STX(u & 1, exA[u], exB[u]);
                RENORMF(1);
                {   // lane-parallel numerator
                    int tgu = *(const int*)(gb + 416 + ((size_t)l << (2 + tshift)));
                    int tgp = (l == 0) ? tagPrev
                        : *(const int*)(gb + 416 + ((size_t)(l - 1) << (2 + tshift)));
                    float rt = *(const float*)(gb + l * 52 + tgu * 4);
                    numL += sm_trans[tgp * K_ + tgu] + rt;
                    tagPrev = __shfl_sync(0xffffffffu, tgu, 7, 8);
                }
                last = tagPrev; prev = tagPrev;
            } else {
                prev = tagPrev;
#pragma unroll
                for (int u = 0; u < 8; u++) {
                    float eA = *(const float*)(gb + u * 52 + oAl * 4);
                    float eB = *(const float*)(gb + u * 52 + oBl * 4);
                    int   tg = *(const int*)(gb + 416 + ((size_t)u << (2 + tshift)));
                    int   mk = gb[480 + (u << msh)];
                    float rt = *(const float*)(gb + u * 52 + tg * 4);
                    STEPF_GEN(u & 1, eA, eB, tg, mk, rt);
                }
                RENORMF(1);
                tagPrev = prev;
            }
        }

#pragma unroll
        for (int d = 1; d < 8; d <<= 1)
            numL += __shfl_xor_sync(0xffffffffu, numL, d, 8);
        num += numL;

        ((float2*)g_svF[batch])[l] = make_float2(sA, sB);
        __syncwarp();
        if (l == 0) {
            g_numF[batch] = num; g_mexF[batch] = Mexp; g_lastF[batch] = last;
            __threadfence();
            g_flag[batch] = 1;
        }
    } else {
        // ======== BACKWARD: t = 511 .. 256 (copy chunks 0..32, base 504-8c) ====
        unsigned long long etEA[4], etEB[4];
#pragma unroll
        for (int j = 0; j < 4; j++) {
            int t0 = ORIG(4 * j), t1 = ORIG(4 * j + 2);
            float a0 = (vA_ && t0 >= 0) ? __expf(sm_trans[oA * K_ + t0]) : 0.0f;
            float a1 = (vA_ && t1 >= 0) ? __expf(sm_trans[oA * K_ + t1]) : 0.0f;
            float b0 = (vB_ && t0 >= 0) ? __expf(sm_trans[oB * K_ + t0]) : 0.0f;
            float b1 = (vB_ && t1 >= 0) ? __expf(sm_trans[oB * K_ + t1]) : 0.0f;
            etEA[j] = pk2(a0, a1);
            etEB[j] = pk2(b0, b1);
        }
        const float cSA = (vA_ && vB_) ? __expf(sm_trans[oA * K_ + oB]) : 0.0f;
        const float cSB = vB_ ? __expf(sm_trans[oB * K_ + oB]) : 0.0f;

        float wA = vA_ ? __expf(sm_end[oAl]) : 0.0f;
        float wB = vB_ ? __expf(sm_end[oBl]) : 0.0f;
        float vE   = vA_ ? wA * __expf(row[511 * K_ + oAl]) : 0.0f;
        float vOdd = vB_ ? wB * __expf(row[511 * K_ + oBl]) : 0.0f;
        int Mexp = 0, lastB = 0, anyB = 0;
        float num = 0.0f;
        int tHi = tags_words[(tbase + 511) << tshift];
        STORE1(0, vE);

#define STEPB_MV(W)                                                           \
        float mA, mB;                                                         \
        {                                                                     \
            unsigned _ra = xch_addr + (((W) ^ 1) * 320);                      \
            unsigned long long q0,q1,q2,q3;                                   \
            asm volatile("ld.shared.v2.u64 {%0,%1},[%2];"                     \
                         : "=l"(q0),"=l"(q1) : "r"(_ra));                     \
            asm volatile("ld.shared.v2.u64 {%0,%1},[%2+16];"                  \
                         : "=l"(q2),"=l"(q3) : "r"(_ra));                     \
            unsigned long long a0 = mul2(q0, etEA[0]);                        \
            unsigned long long a1 = mul2(q1, etEA[1]);                        \
            a0 = fma2(q2, etEA[2], a0);  a1 = fma2(q3, etEA[3], a1);          \
            unsigned long long b0 = mul2(q0, etEB[0]);                        \
            unsigned long long b1 = mul2(q1, etEB[1]);                        \
            b0 = fma2(q2, etEB[2], b0);  b1 = fma2(q3, etEB[3], b1);          \
            float xA,yA,xB,yB;                                                \
            upk2(add2(a0, a1), xA, yA);                                       \
            upk2(add2(b0, b1), xB, yB);                                       \
            mA = fmaf(cSA, vOdd, xA + yA);                                    \
            mB = fmaf(cSB, vOdd, xB + yB);                                    \
        }
#define STEPB_STX(W, exfa, exfb) {                                            \
        STEPB_MV(W);                                                          \
        wA = mA; wB = mB;                                                     \
        vE = (exfa) * wA;  vOdd = (exfb) * wB;                                \
        STORE1(W, vE); }
#define STEPB_GEN(W, fAv, fBv, tLov, mkv, rtv) {                              \
        STEPB_MV(W);                                                          \
        bool _mk = (mkv) != 0;                                                \
        wA = _mk ? mA : wA;  wB = _mk ? mB : wB;                              \
        num += _mk ? (sm_trans[(tLov) * K_ + tHi] + (rtv)) : 0.0f;            \
        lastB = (_mk && !anyB) ? tHi : lastB;  anyB |= (int)_mk;              \
        tHi = (tLov);                                                         \
        vE = __expf(fAv) * wA;  vOdd = __expf(fBv) * wB;                      \
        STORE1(W, vE); }
#define RENORMB() {                                                           \
        float sO;                                                             \
        asm volatile("ld.shared.f32 %0,[%1];"                                 \
                     : "=f"(sO) : "r"(xch_addr + 24));                        \
        int ebx = (__float_as_int(sO) >> 23) & 255;                           \
        float scx = __int_as_float((254 - ebx) << 23);                        \
        wA *= scx; wB *= scx; vE *= scx; vOdd *= scx; Mexp += ebx - 127;      \
        STORE1(0, vE); }

        COPY_ROWS(504, bufs_[0]);   // chunk 0
        COPY_ROWS(496, bufs_[1]);   // chunk 1
        for (int c = 0; c < 32; c++) {
            int cn = (c + 2 < 33) ? c + 2 : 32;            // chunk 32 = base 248
            COPY_ROWS(504 - 8 * cn, bufs_[(c + 2) % 3]);
            cp_wait<2>();                                   // chunk c guaranteed
            __syncwarp();
            const unsigned char* gbC = bufp[c % 3];
            const unsigned char* gbN = bufp[(c + 1) % 3];
            if (mask_ones(gbC, msh)) {
                float exFA[7], exFB[7];
#pragma unroll
                for (int u = 0; u < 7; u++) {
                    exFA[u] = __expf(*(const float*)(gbC + (6 - u) * 52 + oAl * 4));
                    exFB[u] = __expf(*(const float*)(gbC + (6 - u) * 52 + oBl * 4));
                }
#pragma unroll
                for (int u = 0; u < 7; u++)
                    STEPB_STX((u & 1) ^ 1, exFA[u], exFB[u]);
                cp_wait<1>();                               // chunk c+1 guaranteed
                __syncwarp();
                {
                    float fa = __expf(*(const float*)(gbN + 7 * 52 + oAl * 4));
                    float fb = __expf(*(const float*)(gbN + 7 * 52 + oBl * 4));
                    STEPB_STX(0, fa, fb);
                }
                RENORMB();
                {   // lane-parallel numerator
                    int off = 7 - l;
                    int tg_t = *(const int*)(gbC + 416 + ((size_t)off << (2 + tshift)));
                    int tg_p = (l == 7)
                        ? *(const int*)(gbN + 416 + ((size_t)7 << (2 + tshift)))
                        : *(const int*)(gbC + 416 + ((size_t)(off - 1) << (2 + tshift)));
                    float rt = *(const float*)(gbC + off * 52 + tg_t * 4);
                    numL += sm_trans[tg_p * K_ + tg_t] + rt;
                    lastB = anyB ? lastB : __shfl_sync(0xffffffffu, tg_t, 0, 8);
                    anyB = 1;
                    tHi = __shfl_sync(0xffffffffu, tg_p, 7, 8);
                }
            } else {
#pragma unroll
                for (int u = 0; u < 7; u++) {
                    float fA = *(const float*)(gbC + (6 - u) * 52 + oAl * 4);
                    float fB = *(const float*)(gbC + (6 - u) * 52 + oBl * 4);
                    int  tLo = *(const int*)(gbC + 416 + ((size_t)(6 - u) << (2 + tshift)));
                    int   mk = gbC[480 + ((7 - u) << msh)];
                    float rt = *(const float*)(gbC + (7 - u) * 52 + tHi * 4);
                    STEPB_GEN((u & 1) ^ 1, fA, fB, tLo, mk, rt);
                }
                cp_wait<1>();
                __syncwarp();
                {
                    float fA = *(const float*)(gbN + 7 * 52 + oAl * 4);
                    float fB = *(const float*)(gbN + 7 * 52 + oBl * 4);
                    int  tLo = *(const int*)(gbN + 416 + ((size_t)7 << (2 + tshift)));
                    int   mk = gbC[480 + (0 << msh)];
                    float rt = *(const float*)(gbC + 0 * 52 + tHi * 4);
                    STEPB_GEN(0, fA, fB, tLo, mk, rt);
                }
                RENORMB();
            }
        }

#pragma unroll
        for (int d = 1; d < 8; d <<= 1)
            numL += __shfl_xor_sync(0xffffffffu, numL, d, 8);
        num += numL;

        // ---- combine ----
        volatile int* fl = &g_flag[batch];
        while (*fl == 0) __nanosleep(128);
        __threadfence();
        float2 af = ((const float2*)g_svF[batch])[l];
        float dot = af.x * wA + af.y * wB;
#pragma unroll
        for (int d = 1; d < 8; d <<= 1)
            dot += __shfl_xor_sync(0xffffffffu, dot, d, 8);
        if (l == 0) {
            int   lf   = g_lastF[batch];
            int   mexF = g_mexF[batch];
            float numF = g_numF[batch];
            int lastT = anyB ? lastB : lf;
            float numT = numF + num + end_t[lastT];
            float denom = (float)(mexF + Mexp) * 0.6931471805599453f + __logf(dot);
            long long q = llrintf((numT - denom) * 1048576.0f);
            atomicAdd(&g_acc, (unsigned long long)q);
            __threadfence();
            unsigned t = atomicAdd(&g_cnt, 1u);
            if (t == B_ - 1) {
                unsigned long long tot = *(volatile unsigned long long*)&g_acc;
                out[0] = (float)((double)(long long)tot * 9.5367431640625e-7);
                *(volatile unsigned long long*)&g_acc = 0;
                *(volatile unsigned int*)&g_cnt = 0;
                __threadfence();
            }
        }
        __syncwarp();
        if (l == 0) *fl = 0;
    }
}

extern "C" void kernel_launch(void* const* d_in, const int* in_sizes, int n_in,
                              void* d_out, int out_size)
{
    const float*         emissions = (const float*)d_in[0];
    const int*           tags_w    = (const int*)d_in[1];
    const unsigned char* mask_b    = (const unsigned char*)d_in[2];
    const float*         start_t   = (const float*)d_in[3];
    const float*         end_t     = (const float*)d_in[4];
    const float*         trans     = (const float*)d_in[5];
    float*               out       = (float*)d_out;

    crf_half_kernel<<<512, 128>>>(emissions, tags_w, mask_b,
                                  (const unsigned int*)d_in[2],
                                  start_t, end_t, trans, out);
}

// round 16
// speedup vs baseline: 1.1583x; 1.1583x over previous
#include <cuda_runtime.h>

// CRF log-likelihood: B=4096, T=512, K=13.
// Best-known structure (8-lane groups, permuted states, split fwd/bwd halves,
// lane-parallel numerator, double-buffered cp.async) repackaged as
// ONE WARP PER BLOCK (2048 blocks) to kill the 4-vs-3-blocks/SM imbalance.
#define B_ 4096
#define T_ 512
#define K_ 13
#define GSTRIDE 544

__device__ __align__(16) float g_svF[B_][16];
__device__ float g_numF[B_];
__device__ int   g_mexF[B_], g_lastF[B_];
__device__ volatile int g_flag[B_];
__device__ unsigned long long g_acc = 0;
__device__ unsigned int       g_cnt = 0;

__device__ __forceinline__ void cp16(unsigned dst, const void* src) {
    asm volatile("cp.async.cg.shared.global [%0], [%1], 16;\n" :: "r"(dst), "l"(src));
}
__device__ __forceinline__ void cp8(unsigned dst, const void* src) {
    asm volatile("cp.async.ca.shared.global [%0], [%1], 8;\n" :: "r"(dst), "l"(src));
}
__device__ __forceinline__ void cp_commit() { asm volatile("cp.async.commit_group;\n"); }
template<int N> __device__ __forceinline__ void cp_wait() {
    asm volatile("cp.async.wait_group %0;\n" :: "n"(N));
}
__device__ __forceinline__ unsigned long long pk2(float lo, float hi) {
    unsigned long long r;
    asm("mov.b64 %0,{%1,%2};" : "=l"(r) : "f"(lo), "f"(hi));
    return r;
}
__device__ __forceinline__ void upk2(unsigned long long v, float& lo, float& hi) {
    asm("mov.b64 {%0,%1},%2;" : "=f"(lo), "=f"(hi) : "l"(v));
}
__device__ __forceinline__ unsigned long long mul2(unsigned long long a, unsigned long long b) {
    unsigned long long d;
    asm("mul.rn.f32x2 %0,%1,%2;" : "=l"(d) : "l"(a), "l"(b));
    return d;
}
__device__ __forceinline__ unsigned long long fma2(unsigned long long a, unsigned long long b,
                                                   unsigned long long c) {
    unsigned long long d;
    asm("fma.rn.f32x2 %0,%1,%2,%3;" : "=l"(d) : "l"(a), "l"(b), "l"(c));
    return d;
}
__device__ __forceinline__ unsigned long long add2(unsigned long long a, unsigned long long b) {
    unsigned long long d;
    asm("add.rn.f32x2 %0,%1,%2;" : "=l"(d) : "l"(a), "l"(b));
    return d;
}
__device__ __forceinline__ int ORIG(int n) { return n < 12 ? n + 1 : (n == 12 ? 0 : -1); }

__device__ __forceinline__ bool mask_ones(const unsigned char* gb, int msh) {
    const unsigned long long* mw = (const unsigned long long*)(gb + 480);
    if (msh) return (mw[0] == 0x0000000100000001ULL) & (mw[1] == 0x0000000100000001ULL)
                  & (mw[2] == 0x0000000100000001ULL) & (mw[3] == 0x0000000100000001ULL);
    return mw[0] == 0x0101010101010101ULL;
}

#define STORE2(W, a, b)                                                       \
    asm volatile("st.shared.v2.f32 [%0],{%1,%2};"                             \
                 :: "r"(xch_addr + (W) * 320 + l * 8), "f"(a), "f"(b) : "memory");
#define STORE1(W, a)                                                          \
    asm volatile("st.shared.f32 [%0],%1;"                                     \
                 :: "r"(xch_addr + (W) * 320 + l * 4), "f"(a) : "memory");

__global__ void __launch_bounds__(32) crf_half_kernel(
    const float* __restrict__ emissions,
    const int* __restrict__ tags_words,
    const unsigned char* __restrict__ mask_b,
    const unsigned int* __restrict__ mask_words,
    const float* __restrict__ start_t,
    const float* __restrict__ end_t,
    const float* __restrict__ trans,
    float* __restrict__ out)
{
    __shared__ float sm_trans[K_ * K_];
    __shared__ float sm_start[K_];
    __shared__ float sm_end[K_];
    __shared__ __align__(16) unsigned char stage[2 * 4 * GSTRIDE];  // buf,group
    __shared__ __align__(16) float s_xch[2 * 4 * 20];               // par,group
    __shared__ int s_t64, s_m32;

    const int tid = threadIdx.x;   // 0..31
    if (tid == 0) { s_t64 = 1; s_m32 = 1; }
    for (int i = tid; i < K_ * K_; i += 32) sm_trans[i] = trans[i];
    if (tid < K_) { sm_start[tid] = start_t[tid]; sm_end[tid] = end_t[tid]; }
    __syncthreads();
    // tags int64 <=> odd words zero; 64 samples (2 per thread)
    if ((tags_words[2 * tid + 1] | tags_words[2 * tid + 65]) != 0) s_t64 = 0;
    // mask int32 <=> sampled words in {0,1}
    if (mask_words[(blockIdx.x & 1023) * 512 + tid * 16] > 1u) s_m32 = 0;
    __syncthreads();
    const int tshift = s_t64 ? 1 : 0;
    const int msh    = s_m32 ? 2 : 0;

    const bool isF = (blockIdx.x < 1024);
    const int bblk = blockIdx.x & 1023;
    const int lane = tid;
    const int g    = lane >> 3;
    const int l    = lane & 7;
    const int batch = bblk * 4 + g;

    const size_t tbase = (size_t)batch * T_;
    const int oA = ORIG(2 * l);
    const int oB = ORIG(2 * l + 1);
    const bool vA_ = (oA >= 0);
    const bool vB_ = (oB >= 0);
    const int oAl = vA_ ? oA : 0;
    const int oBl = vB_ ? oB : 0;

    const float* __restrict__ row = emissions + (size_t)batch * (T_ * K_);

    unsigned char* buf0 = stage + (size_t)(0 * 4 + g) * GSTRIDE;
    unsigned char* buf1 = stage + (size_t)(1 * 4 + g) * GSTRIDE;
    const unsigned buf0s = (unsigned)__cvta_generic_to_shared(buf0);
    const unsigned buf1s = (unsigned)__cvta_generic_to_shared(buf1);
    const unsigned xch_addr =
        (unsigned)__cvta_generic_to_shared(s_xch) + g * 80;

#define COPY_ROWS(R0, dsts)                                                   \
    {                                                                         \
        const char* esrc = (const char*)row + (size_t)(R0) * (K_ * 4);        \
        _Pragma("unroll")                                                     \
        for (int it = 0; it < 4; it++) {                                      \
            int idx = l + it * 8;                                             \
            if (idx < 26) cp16((dsts) + idx * 16, esrc + idx * 16);           \
        }                                                                     \
        if (tshift) { if (l < 4) cp16((dsts) + 416 + l * 16,                  \
            (const char*)tags_words + (((size_t)(tbase + (R0))) << 3) + l*16); } \
        else        { if (l < 2) cp16((dsts) + 416 + l * 16,                  \
            (const char*)tags_words + (((size_t)(tbase + (R0))) << 2) + l*16); } \
        if (msh)    { if (l < 2) cp16((dsts) + 480 + l * 16,                  \
            mask_b + (((size_t)(tbase + (R0))) << 2) + l * 16); }             \
        else        { if (l == 0) cp8((dsts) + 480, mask_b + (tbase + (R0))); } \
        cp_commit();                                                          \
    }

    float numL = 0.0f;

    if (isF) {
        // ======== FORWARD: t = 0 .. 255 ========
        unsigned long long etpA[8];
#pragma unroll
        for (int i = 0; i < 8; i++) {
            int r0 = ORIG(2 * i), r1 = ORIG(2 * i + 1);
            float a0 = (vA_ && r0 >= 0) ? __expf(sm_trans[r0 * K_ + oA]) : 0.0f;
            float a1 = (vA_ && r1 >= 0) ? __expf(sm_trans[r1 * K_ + oA]) : 0.0f;
            etpA[i] = pk2(a0, a1);
        }
        const float cB0 = vB_ ? __expf(sm_trans[oA * K_ + oB]) : 0.0f;
        const float cB1 = vB_ ? __expf(sm_trans[oB * K_ + oB]) : 0.0f;

        float sA = vA_ ? __expf(sm_start[oAl] + row[oAl]) : 0.0f;
        float sB = vB_ ? __expf(sm_start[oBl] + row[oBl]) : 0.0f;
        int Mexp;
        {
            float rawO = __expf(sm_start[0] + row[0]);   // state O, always > 0
            int eb = (__float_as_int(rawO) >> 23) & 255;
            float sc = __int_as_float((254 - eb) << 23);
            sA *= sc; sB *= sc; Mexp = eb - 127;
        }
        int tg0 = tags_words[tbase << tshift];
        float num = sm_start[tg0] + row[tg0];
        int prev = tg0, last = tg0;
        STORE2(0, sA, sB);

#define STEPF_MV(W)                                                           \
        float mA, mB;                                                         \
        {                                                                     \
            unsigned _ra = xch_addr + (((W) ^ 1) * 320);                      \
            unsigned long long q0,q1,q2,q3,q4,q5,q6,q7;                       \
            asm volatile("ld.shared.v2.u64 {%0,%1},[%2];"                     \
                         : "=l"(q0),"=l"(q1) : "r"(_ra));                     \
            asm volatile("ld.shared.v2.u64 {%0,%1},[%2+16];"                  \
                         : "=l"(q2),"=l"(q3) : "r"(_ra));                     \
            asm volatile("ld.shared.v2.u64 {%0,%1},[%2+32];"                  \
                         : "=l"(q4),"=l"(q5) : "r"(_ra));                     \
            asm volatile("ld.shared.v2.u64 {%0,%1},[%2+48];"                  \
                         : "=l"(q6),"=l"(q7) : "r"(_ra));                     \
            unsigned long long a0 = mul2(q0, etpA[0]);                        \
            unsigned long long a1 = mul2(q1, etpA[1]);                        \
            a0 = fma2(q2, etpA[2], a0);  a1 = fma2(q3, etpA[3], a1);          \
            a0 = fma2(q4, etpA[4], a0);  a1 = fma2(q5, etpA[5], a1);          \
            a0 = fma2(q6, etpA[6], a0);  a1 = fma2(q7, etpA[7], a1);          \
            float xA, yA;  upk2(add2(a0, a1), xA, yA);                        \
            mA = xA + yA;                                                     \
            mB = fmaf(cB1, sB, cB0 * sA);  /* own-pair I-column */            \
        }
#define STEPF_ST(W, eAv, eBv) {                                               \
        STEPF_MV(W);                                                          \
        sA = __expf(eAv) * mA;  sB = __expf(eBv) * mB;                        \
        STORE2(W, sA, sB); }
#define STEPF_GEN(W, eAv, eBv, tgv, mkv, rtv) {                               \
        STEPF_MV(W);                                                          \
        float rA = __expf(eAv) * mA;                                          \
        float rB = __expf(eBv) * mB;                                          \
        bool _mk = (mkv) != 0;                                                \
        sA = _mk ? rA : sA;  sB = _mk ? rB : sB;                              \
        num += _mk ? (sm_trans[prev * K_ + (tgv)] + (rtv)) : 0.0f;            \
        last = _mk ? (tgv) : last;  prev = (tgv);                             \
        STORE2(W, sA, sB); }
#define RENORMF(W) {                                                          \
        float sO;                                                             \
        asm volatile("ld.shared.f32 %0,[%1];"                                 \
                     : "=f"(sO) : "r"(xch_addr + (W) * 320 + 48));            \
        int ebx = (__float_as_int(sO) >> 23) & 255;                           \
        float scx = __int_as_float((254 - ebx) << 23);                        \
        sA *= scx; sB *= scx; Mexp += ebx - 127;                              \
        STORE2(W, sA, sB); }

        COPY_ROWS(8, buf0s);
#pragma unroll
        for (int t = 1; t < 8; t++) {
            const float* r = row + t * K_;
            int tg = tags_words[(tbase + t) << tshift];
            int mk = mask_b[(tbase + t) << msh];
            float eA = r[oAl];
            float eB = r[oBl];
            float rt = r[tg];
            STEPF_GEN(t & 1, eA, eB, tg, mk, rt);
        }
        RENORMF(1);
        int tagPrev = prev;

        for (int c = 0; c < 31; c++) {
            COPY_ROWS(16 + 8 * c, ((c + 1) & 1) ? buf1s : buf0s);
            cp_wait<1>();
            __syncwarp();
            const unsigned char* gb = (c & 1) ? buf1 : buf0;
            if (mask_ones(gb, msh)) {
#pragma unroll
                for (int u = 0; u < 8; u++) {
                    float eA = *(const float*)(gb + u * 52 + oAl * 4);
                    float eB = *(const float*)(gb + u * 52 + oBl * 4);
                    STEPF_ST(u & 1, eA, eB);
                }
                RENORMF(1);
                {   // lane-parallel numerator: lane l handles step l
                    int tgu = *(const int*)(gb + 416 + ((size_t)l << (2 + tshift)));
                    int tgp = (l == 0) ? tagPrev
                        : *(const int*)(gb + 416 + ((size_t)(l - 1) << (2 + tshift)));
                    float rt = *(const float*)(gb + l * 52 + tgu * 4);
                    numL += sm_trans[tgp * K_ + tgu] + rt;
                    tagPrev = __shfl_sync(0xffffffffu, tgu, 7, 8);
                }
                last = tagPrev; prev = tagPrev;
            } else {
                prev = tagPrev;
#pragma unroll
                for (int u = 0; u < 8; u++) {
                    float eA = *(const float*)(gb + u * 52 + oAl * 4);
                    float eB = *(const float*)(gb + u * 52 + oBl * 4);
                    int   tg = *(const int*)(gb + 416 + ((size_t)u << (2 + tshift)));
                    int   mk = gb[480 + (u << msh)];
                    float rt = *(const float*)(gb + u * 52 + tg * 4);
                    STEPF_GEN(u & 1, eA, eB, tg, mk, rt);
                }
                RENORMF(1);
                tagPrev = prev;
            }
        }

#pragma unroll
        for (int d = 1; d < 8; d <<= 1)
            numL += __shfl_xor_sync(0xffffffffu, numL, d, 8);
        num += numL;

        ((float2*)g_svF[batch])[l] = make_float2(sA, sB);
        __syncwarp();
        if (l == 0) {
            g_numF[batch] = num; g_mexF[batch] = Mexp; g_lastF[batch] = last;
            __threadfence();
            g_flag[batch] = 1;
        }
    } else {
        // ======== BACKWARD: t = 511 .. 256, then combine ========
        unsigned long long etEA[4], etEB[4];
#pragma unroll
        for (int j = 0; j < 4; j++) {
            int t0 = ORIG(4 * j), t1 = ORIG(4 * j + 2);
            float a0 = (vA_ && t0 >= 0) ? __expf(sm_trans[oA * K_ + t0]) : 0.0f;
            float a1 = (vA_ && t1 >= 0) ? __expf(sm_trans[oA * K_ + t1]) : 0.0f;
            float b0 = (vB_ && t0 >= 0) ? __expf(sm_trans[oB * K_ + t0]) : 0.0f;
            float b1 = (vB_ && t1 >= 0) ? __expf(sm_trans[oB * K_ + t1]) : 0.0f;
            etEA[j] = pk2(a0, a1);
            etEB[j] = pk2(b0, b1);
        }
        const float cSA = (vA_ && vB_) ? __expf(sm_trans[oA * K_ + oB]) : 0.0f;
        const float cSB = vB_ ? __expf(sm_trans[oB * K_ + oB]) : 0.0f;

        float wA = vA_ ? __expf(sm_end[oAl]) : 0.0f;
        float wB = vB_ ? __expf(sm_end[oBl]) : 0.0f;
        float vE   = vA_ ? wA * __expf(row[511 * K_ + oAl]) : 0.0f;
        float vOdd = vB_ ? wB * __expf(row[511 * K_ + oBl]) : 0.0f;
        int Mexp = 0, lastB = 0, anyB = 0;
        float num = 0.0f;
        int tHi = tags_words[(tbase + 511) << tshift];
        STORE1(0, vE);

#define STEPB_MV(W)                                                           \
        float mA, mB;                                                         \
        {                                                                     \
            unsigned _ra = xch_addr + (((W) ^ 1) * 320);                      \
            unsigned long long q0,q1,q2,q3;                                   \
            asm volatile("ld.shared.v2.u64 {%0,%1},[%2];"                     \
                         : "=l"(q0),"=l"(q1) : "r"(_ra));                     \
            asm volatile("ld.shared.v2.u64 {%0,%1},[%2+16];"                  \
                         : "=l"(q2),"=l"(q3) : "r"(_ra));                     \
            unsigned long long a0 = mul2(q0, etEA[0]);                        \
            unsigned long long a1 = mul2(q1, etEA[1]);                        \
            a0 = fma2(q2, etEA[2], a0);  a1 = fma2(q3, etEA[3], a1);          \
            unsigned long long b0 = mul2(q0, etEB[0]);                        \
            unsigned long long b1 = mul2(q1, etEB[1]);                        \
            b0 = fma2(q2, etEB[2], b0);  b1 = fma2(q3, etEB[3], b1);          \
            float xA,yA,xB,yB;                                                \
            upk2(add2(a0, a1), xA, yA);                                       \
            upk2(add2(b0, b1), xB, yB);                                       \
            mA = fmaf(cSA, vOdd, xA + yA);                                    \
            mB = fmaf(cSB, vOdd, xB + yB);                                    \
        }
#define STEPB_ST(W, fAv, fBv) {                                               \
        STEPB_MV(W);                                                          \
        wA = mA; wB = mB;                                                     \
        vE = __expf(fAv) * wA;  vOdd = __expf(fBv) * wB;                      \
        STORE1(W, vE); }
#define STEPB_GEN(W, fAv, fBv, tLov, mkv, rtv) {                              \
        STEPB_MV(W);                                                          \
        bool _mk = (mkv) != 0;                                                \
        wA = _mk ? mA : wA;  wB = _mk ? mB : wB;                              \
        num += _mk ? (sm_trans[(tLov) * K_ + tHi] + (rtv)) : 0.0f;            \
        lastB = (_mk && !anyB) ? tHi : lastB;  anyB |= (int)_mk;              \
        tHi = (tLov);                                                         \
        vE = __expf(fAv) * wA;  vOdd = __expf(fBv) * wB;                      \
        STORE1(W, vE); }
#define RENORMB() {                                                           \
        float sO;                                                             \
        asm volatile("ld.shared.f32 %0,[%1];"                                 \
                     : "=f"(sO) : "r"(xch_addr + 24));                        \
        int ebx = (__float_as_int(sO) >> 23) & 255;                           \
        float scx = __int_as_float((254 - ebx) << 23);                        \
        wA *= scx; wB *= scx; vE *= scx; vOdd *= scx; Mexp += ebx - 127;      \
        STORE1(0, vE); }

        COPY_ROWS(504, buf0s);
        for (int c = 0; c < 32; c++) {
            int R0n = 504 - 8 * (c + 1);
            COPY_ROWS(R0n, ((c + 1) & 1) ? buf1s : buf0s);
            cp_wait<1>();
            __syncwarp();
            const unsigned char* gbC = (c & 1) ? buf1 : buf0;
            const unsigned char* gbN = (c & 1) ? buf0 : buf1;
            if (mask_ones(gbC, msh)) {
#pragma unroll
                for (int u = 0; u < 7; u++) {
                    float fA = *(const float*)(gbC + (6 - u) * 52 + oAl * 4);
                    float fB = *(const float*)(gbC + (6 - u) * 52 + oBl * 4);
                    STEPB_ST((u & 1) ^ 1, fA, fB);
                }
                cp_wait<0>();
                __syncwarp();
                {
                    float fA = *(const float*)(gbN + 7 * 52 + oAl * 4);
                    float fB = *(const float*)(gbN + 7 * 52 + oBl * 4);
                    STEPB_ST(0, fA, fB);
                }
                RENORMB();
                {   // lane-parallel numerator: lane l handles t-offset 7-l
                    int off = 7 - l;
                    int tg_t = *(const int*)(gbC + 416 + ((size_t)off << (2 + tshift)));
                    int tg_p = (l == 7)
                        ? *(const int*)(gbN + 416 + ((size_t)7 << (2 + tshift)))
                        : *(const int*)(gbC + 416 + ((size_t)(off - 1) << (2 + tshift)));
                    float rt = *(const float*)(gbC + off * 52 + tg_t * 4);
                    numL += sm_trans[tg_p * K_ + tg_t] + rt;
                    lastB = anyB ? lastB : __shfl_sync(0xffffffffu, tg_t, 0, 8);
                    anyB = 1;
                    tHi = __shfl_sync(0xffffffffu, tg_p, 7, 8);
                }
            } else {
#pragma unroll
                for (int u = 0; u < 7; u++) {
                    float fA = *(const float*)(gbC + (6 - u) * 52 + oAl * 4);
                    float fB = *(const float*)(gbC + (6 - u) * 52 + oBl * 4);
                    int  tLo = *(const int*)(gbC + 416 + ((size_t)(6 - u) << (2 + tshift)));
                    int   mk = gbC[480 + ((7 - u) << msh)];
                    float rt = *(const float*)(gbC + (7 - u) * 52 + tHi * 4);
                    STEPB_GEN((u & 1) ^ 1, fA, fB, tLo, mk, rt);
                }
                cp_wait<0>();
                __syncwarp();
                {
                    float fA = *(const float*)(gbN + 7 * 52 + oAl * 4);
                    float fB = *(const float*)(gbN + 7 * 52 + oBl * 4);
                    int  tLo = *(const int*)(gbN + 416 + ((size_t)7 << (2 + tshift)));
                    int   mk = gbC[480 + (0 << msh)];
                    float rt = *(const float*)(gbC + 0 * 52 + tHi * 4);
                    STEPB_GEN(0, fA, fB, tLo, mk, rt);
                }
                RENORMB();
            }
        }

#pragma unroll
        for (int d = 1; d < 8; d <<= 1)
            numL += __shfl_xor_sync(0xffffffffu, numL, d, 8);
        num += numL;

        // ---- combine (fwd blocks launch/schedule first; all co-resident) ----
        volatile int* fl = &g_flag[batch];
        while (*fl == 0) __nanosleep(128);
        __threadfence();
        float2 af = ((const float2*)g_svF[batch])[l];
        float dot = af.x * wA + af.y * wB;
#pragma unroll
        for (int d = 1; d < 8; d <<= 1)
            dot += __shfl_xor_sync(0xffffffffu, dot, d, 8);
        if (l == 0) {
            int   lf   = g_lastF[batch];
            int   mexF = g_mexF[batch];
            float numF = g_numF[batch];
            int lastT = anyB ? lastB : lf;
            float numT = numF + num + end_t[lastT];
            float denom = (float)(mexF + Mexp) * 0.6931471805599453f + __logf(dot);
            long long q = llrintf((numT - denom) * 1048576.0f);
            atomicAdd(&g_acc, (unsigned long long)q);
            __threadfence();
            unsigned t = atomicAdd(&g_cnt, 1u);
            if (t == B_ - 1) {
                unsigned long long tot = *(volatile unsigned long long*)&g_acc;
                out[0] = (float)((double)(long long)tot * 9.5367431640625e-7);
                *(volatile unsigned long long*)&g_acc = 0;
                *(volatile unsigned int*)&g_cnt = 0;
                __threadfence();
            }
        }
        __syncwarp();
        if (l == 0) *fl = 0;
    }
}

extern "C" void kernel_launch(void* const* d_in, const int* in_sizes, int n_in,
                              void* d_out, int out_size)
{
    const float*         emissions = (const float*)d_in[0];
    const int*           tags_w    = (const int*)d_in[1];
    const unsigned char* mask_b    = (const unsigned char*)d_in[2];
    const float*         start_t   = (const float*)d_in[3];
    const float*         end_t     = (const float*)d_in[4];
    const float*         trans     = (const float*)d_in[5];
    float*               out       = (float*)d_out;

    // 2048 single-warp blocks: 1024 forward halves + 1024 backward halves.
    crf_half_kernel<<<2048, 32>>>(emissions, tags_w, mask_b,
                                  (const unsigned int*)d_in[2],
                                  start_t, end_t, trans, out);
}